// round 3
// baseline (speedup 1.0000x reference)
#include <cuda_runtime.h>

// HistPredictor: splat B*K 2D Gaussians onto 128x128 grids, normalize per batch.
// B=256, K=16, grid 128x128 over [-2,2]^2, MIN_SIGMA=0.001.
//
// R3: two-phase. Phase A: 1024 CTAs (quarter-batches) for near-perfect SM
// balance, packed f32x2 incremental exponent + packed accumulate, EX2 on MUFU.
// Phase B: per-batch normalization (L2-resident traffic).

#define KMIX 16

__device__ float g_part[1024];   // per-(batch,quarter) partial sums

__device__ __forceinline__ float ex2f(float x) {
    float r;
    asm("ex2.approx.f32 %0, %1;" : "=f"(r) : "f"(x));
    return r;
}
__device__ __forceinline__ unsigned long long pack2(float lo, float hi) {
    unsigned long long r;
    asm("mov.b64 %0, {%1, %2};" : "=l"(r) : "f"(lo), "f"(hi));
    return r;
}
__device__ __forceinline__ void unpack2(float& lo, float& hi, unsigned long long p) {
    asm("mov.b64 {%0, %1}, %2;" : "=f"(lo), "=f"(hi) : "l"(p));
}
__device__ __forceinline__ unsigned long long add2(unsigned long long a, unsigned long long b) {
    unsigned long long r;
    asm("add.rn.f32x2 %0, %1, %2;" : "=l"(r) : "l"(a), "l"(b));
    return r;
}
__device__ __forceinline__ unsigned long long fma2(unsigned long long a, unsigned long long b,
                                                   unsigned long long c) {
    unsigned long long r;
    asm("fma.rn.f32x2 %0, %1, %2, %3;" : "=l"(r) : "l"(a), "l"(b), "l"(c));
    return r;
}

__global__ __launch_bounds__(128, 8)
void gmm_hist_phaseA(const float* __restrict__ mu,
                     const float* __restrict__ sigma,
                     const float* __restrict__ cov12,
                     const float* __restrict__ pi,
                     float* __restrict__ out)
{
    // log2-domain coefficients: e2 = a2*du^2 + b2*du*dv + c2*dv^2  (<= 0)
    __shared__ float s_a[KMIX], s_b[KMIX], s_c[KMIX], s_c2[KMIX];
    __shared__ float s_mu[KMIX], s_mv[KMIX], s_coef[KMIX];
    __shared__ float s_R[KMIX], s_S[KMIX], s_R8[KMIX];
    __shared__ float s_red[4];

    const int blk = blockIdx.x;
    const int b = blk >> 2;        // batch
    const int q = blk & 3;         // u-quarter
    const int t = threadIdx.x;

    const float H   = 4.0f / 127.0f;
    const float L2E = 1.4426950408889634f;

    if (t < KMIX) {
        const int idx = b * KMIX + t;
        float su = fmaxf(sigma[idx * 2 + 0], 0.001f);
        float sv = fmaxf(sigma[idx * 2 + 1], 0.001f);
        float su2 = su * su;
        float sv2 = sv * sv;
        float c11 = su2 + 1e-6f;
        float c22 = sv2 + 1e-6f;
        float off = cov12[idx];
        float det_full = c11 * c22 - off * off;
        // valid = (det_full > 0) & ~isnan(det_full); NaN>0 is false -> covered.
        float ia, ib, ic, det;
        if (det_full > 0.0f) {
            float rdet = 1.0f / det_full;
            ia = c22 * rdet;
            ib = -off * rdet;
            ic = c11 * rdet;
            det = det_full;
        } else {
            ia = 1.0f / su2;
            ib = 0.0f;
            ic = 1.0f / sv2;
            det = su2 * sv2;
        }
        float a2 = -0.5f * L2E * ia;
        float b2 = -L2E * ib;
        float c2 = -0.5f * L2E * ic;   // strictly < 0
        s_a[t]  = a2;
        s_b[t]  = b2;
        s_c[t]  = c2;
        s_c2[t] = 2.0f * c2;
        float R = c2 * (H * H);        // quadratic-in-j coefficient, < 0
        s_R[t]  = R;
        s_R8[t] = 8.0f * R;
        s_S[t]  = -0.5f / R;
        s_mu[t] = mu[idx * 2 + 0];
        s_mv[t] = mu[idx * 2 + 1];
        s_coef[t] = pi[idx] / (6.283185307179586f * sqrtf(det + 1e-6f));
    }
    __syncthreads();

    // Thread t owns u = q*32 + (t>>2), v in [(t&3)*32, +32)
    const int u  = q * 32 + (t >> 2);
    const int v0 = (t & 3) * 32;
    const float uc    = -2.0f + (float)u  * H;
    const float vbase = -2.0f + (float)v0 * H;

    unsigned long long acc[16];      // packed pairs (j even, j odd)
#pragma unroll
    for (int i = 0; i < 16; i++) acc[i] = 0ull;

#pragma unroll 1
    for (int k = 0; k < KMIX; k++) {
        const float du  = uc    - s_mu[k];
        const float dv0 = vbase - s_mv[k];
        // e(j) = P + Q*j + R*j^2,  dv = dv0 + j*H
        const float R = s_R[k];
        const float Q = fmaf(s_c2[k], dv0, s_b[k] * du) * H;
        const float P = fmaf(fmaf(s_b[k], dv0, s_a[k] * du), du, (s_c[k] * dv0) * dv0);

        // warp-uniform skip: max of concave e over j in [0,31]
        float jc = fminf(fmaxf(Q * s_S[k], 0.0f), 31.0f);
        float ev = fmaf(jc, fmaf(R, jc, Q), P);
        if (__ballot_sync(0xffffffffu, ev >= -30.0f) == 0u) continue;

        const float coef = s_coef[k];
        const unsigned long long coefp = pack2(coef, coef);
        // pair state: e = (e(2i), e(2i+1)),  d = (e(2i+2)-e(2i), e(2i+3)-e(2i+1))
        unsigned long long ep = pack2(P, P + Q + R);
        unsigned long long dp = pack2(2.0f * Q + 4.0f * R, 2.0f * Q + 8.0f * R);
        const unsigned long long stp = pack2(s_R8[k], s_R8[k]);

#pragma unroll
        for (int i = 0; i < 16; i++) {
            float elo, ehi;
            unpack2(elo, ehi, ep);
            unsigned long long gp = pack2(ex2f(elo), ex2f(ehi));
            acc[i] = fma2(coefp, gp, acc[i]);
            ep = add2(ep, dp);
            dp = add2(dp, stp);
        }
    }

    // partial sum over this CTA (quarter batch)
    float s = 0.0f;
#pragma unroll
    for (int i = 0; i < 16; i++) {
        float lo, hi;
        unpack2(lo, hi, acc[i]);
        s += lo + hi;
    }
#pragma unroll
    for (int o = 16; o > 0; o >>= 1) s += __shfl_xor_sync(0xffffffffu, s, o);
    const int warp = t >> 5;
    const int lane = t & 31;
    if (lane == 0) s_red[warp] = s;
    __syncthreads();
    if (t == 0) g_part[blk] = s_red[0] + s_red[1] + s_red[2] + s_red[3];

    // unnormalized store (coalesced float4)
    float* op = out + (size_t)b * 16384 + (size_t)u * 128 + v0;
#pragma unroll
    for (int i = 0; i < 16; i += 2) {
        float x0, x1, x2, x3;
        unpack2(x0, x1, acc[i]);
        unpack2(x2, x3, acc[i + 1]);
        *reinterpret_cast<float4*>(op + i * 2) = make_float4(x0, x1, x2, x3);
    }
}

__global__ __launch_bounds__(256)
void gmm_hist_phaseB(float* __restrict__ out)
{
    const int b = blockIdx.x;
    const int t = threadIdx.x;
    float s = g_part[4 * b] + g_part[4 * b + 1] + g_part[4 * b + 2] + g_part[4 * b + 3];
    float inv = (s > 0.0f) ? (1.0f / s) : 1.0f;

    float4* p = reinterpret_cast<float4*>(out + (size_t)b * 16384);
#pragma unroll
    for (int i = 0; i < 16; i++) {
        int idx = t + i * 256;     // 4096 float4 per batch
        float4 w = p[idx];
        w.x *= inv; w.y *= inv; w.z *= inv; w.w *= inv;
        p[idx] = w;
    }
}

extern "C" void kernel_launch(void* const* d_in, const int* in_sizes, int n_in,
                              void* d_out, int out_size)
{
    const float* mu    = (const float*)d_in[0];
    const float* sigma = (const float*)d_in[1];
    const float* cov12 = (const float*)d_in[2];
    const float* pi    = (const float*)d_in[3];
    float* out = (float*)d_out;
    gmm_hist_phaseA<<<1024, 128>>>(mu, sigma, cov12, pi, out);
    gmm_hist_phaseB<<<256, 256>>>(out);
}

// round 4
// speedup vs baseline: 1.1750x; 1.1750x over previous
#include <cuda_runtime.h>
#include <cstdint>

// HistPredictor: splat B*K 2D Gaussians onto 128x128 grids, normalize per batch.
// B=256, K=16, grid 128x128 over [-2,2]^2, MIN_SIGMA=0.001.
//
// R4: single kernel. 4-CTA cluster = one batch (4 u-quarters). Partial sums
// exchanged via DSMEM + barrier.cluster; normalization fused into the store.
// Inner loop: packed f32x2 incremental exponent in log2 domain + EX2 (MUFU).

#define KMIX 16

__device__ __forceinline__ float ex2f(float x) {
    float r;
    asm("ex2.approx.f32 %0, %1;" : "=f"(r) : "f"(x));
    return r;
}
__device__ __forceinline__ unsigned long long pack2(float lo, float hi) {
    unsigned long long r;
    asm("mov.b64 %0, {%1, %2};" : "=l"(r) : "f"(lo), "f"(hi));
    return r;
}
__device__ __forceinline__ void unpack2(float& lo, float& hi, unsigned long long p) {
    asm("mov.b64 {%0, %1}, %2;" : "=f"(lo), "=f"(hi) : "l"(p));
}
__device__ __forceinline__ unsigned long long add2(unsigned long long a, unsigned long long b) {
    unsigned long long r;
    asm("add.rn.f32x2 %0, %1, %2;" : "=l"(r) : "l"(a), "l"(b));
    return r;
}
__device__ __forceinline__ unsigned long long fma2(unsigned long long a, unsigned long long b,
                                                   unsigned long long c) {
    unsigned long long r;
    asm("fma.rn.f32x2 %0, %1, %2, %3;" : "=l"(r) : "l"(a), "l"(b), "l"(c));
    return r;
}

__global__ __launch_bounds__(128, 8) __cluster_dims__(4, 1, 1)
void gmm_hist_kernel(const float* __restrict__ mu,
                     const float* __restrict__ sigma,
                     const float* __restrict__ cov12,
                     const float* __restrict__ pi,
                     float* __restrict__ out)
{
    // log2-domain coefficients: e2 = a2*du^2 + b2*du*dv + c2*dv^2  (<= 0)
    __shared__ float s_a[KMIX], s_b[KMIX], s_c[KMIX], s_c2[KMIX];
    __shared__ float s_mu[KMIX], s_mv[KMIX], s_coef[KMIX];
    __shared__ float s_R[KMIX], s_S[KMIX], s_R8[KMIX];
    __shared__ float s_red[4];
    __shared__ float s_part[4];   // per-quarter partial sums (filled via DSMEM)

    const int blk = blockIdx.x;
    const int b = blk >> 2;        // batch
    const int q = blk & 3;         // u-quarter == cluster ctarank
    const int t = threadIdx.x;

    const float H   = 4.0f / 127.0f;
    const float L2E = 1.4426950408889634f;

    if (t < KMIX) {
        const int idx = b * KMIX + t;
        float su = fmaxf(sigma[idx * 2 + 0], 0.001f);
        float sv = fmaxf(sigma[idx * 2 + 1], 0.001f);
        float su2 = su * su;
        float sv2 = sv * sv;
        float c11 = su2 + 1e-6f;
        float c22 = sv2 + 1e-6f;
        float off = cov12[idx];
        float det_full = c11 * c22 - off * off;
        // valid = (det_full > 0) & ~isnan(det_full); NaN>0 is false -> covered.
        float ia, ib, ic, det;
        if (det_full > 0.0f) {
            float rdet = 1.0f / det_full;
            ia = c22 * rdet;
            ib = -off * rdet;
            ic = c11 * rdet;
            det = det_full;
        } else {
            ia = 1.0f / su2;
            ib = 0.0f;
            ic = 1.0f / sv2;
            det = su2 * sv2;
        }
        float a2 = -0.5f * L2E * ia;
        float b2 = -L2E * ib;
        float c2 = -0.5f * L2E * ic;   // strictly < 0
        s_a[t]  = a2;
        s_b[t]  = b2;
        s_c[t]  = c2;
        s_c2[t] = 2.0f * c2;
        float R = c2 * (H * H);        // quadratic-in-j coefficient, < 0
        s_R[t]  = R;
        s_R8[t] = 8.0f * R;
        s_S[t]  = -0.5f / R;
        s_mu[t] = mu[idx * 2 + 0];
        s_mv[t] = mu[idx * 2 + 1];
        s_coef[t] = pi[idx] / (6.283185307179586f * sqrtf(det + 1e-6f));
    }
    __syncthreads();

    // Thread t owns u = q*32 + (t>>2), v in [(t&3)*32, +32)
    const int u  = q * 32 + (t >> 2);
    const int v0 = (t & 3) * 32;
    const float uc    = -2.0f + (float)u  * H;
    const float vbase = -2.0f + (float)v0 * H;

    unsigned long long acc[16];      // packed pairs (j even, j odd)
#pragma unroll
    for (int i = 0; i < 16; i++) acc[i] = 0ull;

#pragma unroll 1
    for (int k = 0; k < KMIX; k++) {
        const float du  = uc    - s_mu[k];
        const float dv0 = vbase - s_mv[k];
        // e(j) = P + Q*j + R*j^2,  dv = dv0 + j*H
        const float R = s_R[k];
        const float Q = fmaf(s_c2[k], dv0, s_b[k] * du) * H;
        const float P = fmaf(fmaf(s_b[k], dv0, s_a[k] * du), du, (s_c[k] * dv0) * dv0);

        // warp-uniform skip: max of concave e over j in [0,31]
        float jc = fminf(fmaxf(Q * s_S[k], 0.0f), 31.0f);
        float ev = fmaf(jc, fmaf(R, jc, Q), P);
        if (__ballot_sync(0xffffffffu, ev >= -30.0f) == 0u) continue;

        const float coef = s_coef[k];
        const unsigned long long coefp = pack2(coef, coef);
        // pair state: e = (e(2i), e(2i+1)),  d = (e(2i+2)-e(2i), e(2i+3)-e(2i+1))
        unsigned long long ep = pack2(P, P + Q + R);
        unsigned long long dp = pack2(2.0f * Q + 4.0f * R, 2.0f * Q + 8.0f * R);
        const unsigned long long stp = pack2(s_R8[k], s_R8[k]);

#pragma unroll
        for (int i = 0; i < 16; i++) {
            float elo, ehi;
            unpack2(elo, ehi, ep);
            unsigned long long gp = pack2(ex2f(elo), ex2f(ehi));
            acc[i] = fma2(coefp, gp, acc[i]);
            ep = add2(ep, dp);
            dp = add2(dp, stp);
        }
    }

    // CTA partial sum (this u-quarter)
    float s = 0.0f;
#pragma unroll
    for (int i = 0; i < 16; i++) {
        float lo, hi;
        unpack2(lo, hi, acc[i]);
        s += lo + hi;
    }
#pragma unroll
    for (int o = 16; o > 0; o >>= 1) s += __shfl_xor_sync(0xffffffffu, s, o);
    const int warp = t >> 5;
    const int lane = t & 31;
    if (lane == 0) s_red[warp] = s;
    __syncthreads();

    // Thread 0 scatters this CTA's partial into slot q of all 4 cluster CTAs.
    if (t == 0) {
        float mysum = s_red[0] + s_red[1] + s_red[2] + s_red[3];
        uint32_t laddr;
        asm("{ .reg .u64 tmp; cvta.to.shared.u64 tmp, %1; cvt.u32.u64 %0, tmp; }"
            : "=r"(laddr) : "l"(&s_part[q]));
#pragma unroll
        for (int r = 0; r < 4; r++) {
            uint32_t raddr;
            asm("mapa.shared::cluster.u32 %0, %1, %2;" : "=r"(raddr) : "r"(laddr), "r"(r));
            asm volatile("st.shared::cluster.f32 [%0], %1;" :: "r"(raddr), "f"(mysum)
                         : "memory");
        }
    }
    // Cluster barrier: arrive(release) orders the DSMEM stores; wait(acquire)
    // makes all 4 partials visible in local s_part.
    asm volatile("barrier.cluster.arrive.aligned;" ::: "memory");
    asm volatile("barrier.cluster.wait.aligned;"   ::: "memory");

    const float tot = (s_part[0] + s_part[1]) + (s_part[2] + s_part[3]);
    const float inv = (tot > 0.0f) ? (1.0f / tot) : 1.0f;

    // normalized store (coalesced float4)
    float* op = out + (size_t)b * 16384 + (size_t)u * 128 + v0;
#pragma unroll
    for (int i = 0; i < 16; i += 2) {
        float x0, x1, x2, x3;
        unpack2(x0, x1, acc[i]);
        unpack2(x2, x3, acc[i + 1]);
        *reinterpret_cast<float4*>(op + i * 2) =
            make_float4(x0 * inv, x1 * inv, x2 * inv, x3 * inv);
    }
}

extern "C" void kernel_launch(void* const* d_in, const int* in_sizes, int n_in,
                              void* d_out, int out_size)
{
    const float* mu    = (const float*)d_in[0];
    const float* sigma = (const float*)d_in[1];
    const float* cov12 = (const float*)d_in[2];
    const float* pi    = (const float*)d_in[3];
    float* out = (float*)d_out;
    gmm_hist_kernel<<<1024, 128>>>(mu, sigma, cov12, pi, out);
}